// round 16
// baseline (speedup 1.0000x reference)
#include <cuda_runtime.h>
#include <math.h>

#define D_     1024
#define BLK    256
#define GRID1  444        // pass1: 3 CTA/SM * 148, single wave
#define GRID2  512        // pass2: 4096 row-groups / 512 = 8 iters exact
#define PAIRS  4
#define NMAX   512
#define MMAX   16384
#define EPS_   1e-5f

typedef unsigned long long ull;
union F4U { float4 f4; ulonglong2 u2; };

// ---- scratch (static device globals; no allocation) ----
__device__ float g_colpart[GRID1 * D_];
__device__ float g_mean[D_];
__device__ float g_gate[MMAX];
__device__ float g_sims[NMAX];
__device__ int   g_valid[NMAX];
__device__ float g_damp, g_qscale;
__device__ int   g_nidx;
__device__ int   g_ctr = 0;
__device__ int   g_ctr2 = 0;

// ---- packed f32x2 helpers ----
__device__ __forceinline__ ull pk2(float lo, float hi) {
    ull r; asm("mov.b64 %0, {%1, %2};" : "=l"(r) : "f"(lo), "f"(hi)); return r;
}
__device__ __forceinline__ float2 upk2(ull v) {
    float2 f; asm("mov.b64 {%0, %1}, %2;" : "=f"(f.x), "=f"(f.y) : "l"(v)); return f;
}
__device__ __forceinline__ ull fma2p(ull a, ull b, ull c) {
    ull r; asm("fma.rn.f32x2 %0, %1, %2, %3;" : "=l"(r) : "l"(a), "l"(b), "l"(c)); return r;
}
__device__ __forceinline__ ull mul2p(ull a, ull b) {
    ull r; asm("mul.rn.f32x2 %0, %1, %2;" : "=l"(r) : "l"(a), "l"(b)); return r;
}
__device__ __forceinline__ float wsum(float v) {
    v += __shfl_xor_sync(0xffffffffu, v, 16);
    v += __shfl_xor_sync(0xffffffffu, v, 8);
    v += __shfl_xor_sync(0xffffffffu, v, 4);
    v += __shfl_xor_sync(0xffffffffu, v, 2);
    v += __shfl_xor_sync(0xffffffffu, v, 1);
    return v;
}
__device__ __forceinline__ float tanh_ap(float u) {
    float r; asm("tanh.approx.f32 %0, %1;" : "=f"(r) : "f"(u)); return r;
}
__device__ __forceinline__ ull gelu2p(ull x2) {
    const ull A2   = pk2(0.044715f, 0.044715f);
    const ull ONE2 = pk2(1.0f, 1.0f);
    const ull C2   = pk2(0.7978845608028654f, 0.7978845608028654f);
    const ull H2   = pk2(0.5f, 0.5f);
    ull t2 = mul2p(x2, x2);
    ull p2 = fma2p(t2, A2, ONE2);
    ull u2 = mul2p(mul2p(x2, C2), p2);
    float2 u = upk2(u2);
    ull T2 = pk2(tanh_ap(u.x), tanh_ap(u.y));
    ull hx2 = mul2p(x2, H2);
    return fma2p(T2, hx2, hx2);
}

// ------ pass 1: warp-pair per row, no block barrier in mainloop ---------
__global__ void __launch_bounds__(BLK, 3) k_pass1(
    const float* __restrict__ x,
    const float* __restrict__ ema_x, const float* __restrict__ ema_x2,
    const float* __restrict__ ema_y, const float* __restrict__ ema_y2,
    const float* __restrict__ p_lt_in, const float* __restrict__ p_lt_out,
    const float* __restrict__ p_la_in, const float* __restrict__ p_la_out,
    int M)
{
    __shared__ float s_buf[4][D_];          // isx / nx / isy / ny, later acc staging
    __shared__ float s_z[2][PAIRS][2][2];   // [parity][pair][half][zx,zy]
    const int t = threadIdx.x;
    const int lane = t & 31, w = t >> 5;
    const int pair = w >> 1, half = w & 1;

    // build ema stat tables in shared (thread t owns cols 4t..4t+3)
    {
        const int c = t * 4;
        float4 ex = *(const float4*)(ema_x + c);
        float4 e2 = *(const float4*)(ema_x2 + c);
        float4 ey = *(const float4*)(ema_y + c);
        float4 f2 = *(const float4*)(ema_y2 + c);
        float4 is, nx, isy, ny;
        is.x = 1.0f / (sqrtf(fmaxf(e2.x - ex.x * ex.x, 0.0f)) + EPS_);
        is.y = 1.0f / (sqrtf(fmaxf(e2.y - ex.y * ex.y, 0.0f)) + EPS_);
        is.z = 1.0f / (sqrtf(fmaxf(e2.z - ex.z * ex.z, 0.0f)) + EPS_);
        is.w = 1.0f / (sqrtf(fmaxf(e2.w - ex.w * ex.w, 0.0f)) + EPS_);
        isy.x = 1.0f / (sqrtf(fmaxf(f2.x - ey.x * ey.x, 0.0f)) + EPS_);
        isy.y = 1.0f / (sqrtf(fmaxf(f2.y - ey.y * ey.y, 0.0f)) + EPS_);
        isy.z = 1.0f / (sqrtf(fmaxf(f2.z - ey.z * ey.z, 0.0f)) + EPS_);
        isy.w = 1.0f / (sqrtf(fmaxf(f2.w - ey.w * ey.w, 0.0f)) + EPS_);
        nx.x = -ex.x * is.x; nx.y = -ex.y * is.y; nx.z = -ex.z * is.z; nx.w = -ex.w * is.w;
        ny.x = -ey.x * isy.x; ny.y = -ey.y * isy.y; ny.z = -ey.z * isy.z; ny.w = -ey.w * isy.w;
        *(float4*)&s_buf[0][c] = is;
        *(float4*)&s_buf[1][c] = nx;
        *(float4*)&s_buf[2][c] = isy;
        *(float4*)&s_buf[3][c] = ny;
    }
    const float tau_in  = expf(p_lt_in[0]);
    const float tau_out = expf(p_lt_out[0]);
    const float a_in    = 1.0f / (1.0f + expf(-p_la_in[0]));
    const float a_out   = 1.0f / (1.0f + expf(-p_la_out[0]));
    const float b_in = 1.0f - a_in, b_out = 1.0f - a_out;
    __syncthreads();

    const int voff = half * 128 + lane;      // float4 index within row
    const int stride = GRID1 * PAIRS;

    ull accA[4], accB[4];
#pragma unroll
    for (int k = 0; k < 4; k++) { accA[k] = 0ull; accB[k] = 0ull; }

    int row = blockIdx.x * PAIRS + pair;
    float4 X[4];
    if (row < M) {
        const float4* xp = (const float4*)(x + (size_t)row * D_) + voff;
#pragma unroll
        for (int k = 0; k < 4; k++) X[k] = xp[32 * k];
    }
    int parity = 0;

    while (row < M) {
        const int rown = row + stride;
        float4 NX[4];
        if (rown < M) {
            const float4* xq = (const float4*)(x + (size_t)rown * D_) + voff;
#pragma unroll
            for (int k = 0; k < 4; k++) NX[k] = xq[32 * k];
        }

        ull Ya[4], Yb[4];
        float zx = 0.f, zy = 0.f;
#pragma unroll
        for (int k = 0; k < 4; k++) {
            F4U Xu; Xu.f4 = X[k];
            ull y0 = gelu2p(Xu.u2.x);
            ull y1 = gelu2p(Xu.u2.y);
            Ya[k] = y0; Yb[k] = y1;
            F4U IS;  IS.f4  = *(const float4*)&s_buf[0][(voff + 32 * k) * 4];
            F4U NXc; NXc.f4 = *(const float4*)&s_buf[1][(voff + 32 * k) * 4];
            F4U ISY; ISY.f4 = *(const float4*)&s_buf[2][(voff + 32 * k) * 4];
            F4U NYc; NYc.f4 = *(const float4*)&s_buf[3][(voff + 32 * k) * 4];
            ull da = fma2p(Xu.u2.x, IS.u2.x, NXc.u2.x);
            ull db = fma2p(Xu.u2.y, IS.u2.y, NXc.u2.y);
            ull sx = fma2p(db, db, mul2p(da, da));
            float2 fx = upk2(sx); zx += fx.x + fx.y;
            ull ga_ = fma2p(y0, ISY.u2.x, NYc.u2.x);
            ull gb_ = fma2p(y1, ISY.u2.y, NYc.u2.y);
            ull sy = fma2p(gb_, gb_, mul2p(ga_, ga_));
            float2 fy = upk2(sy); zy += fy.x + fy.y;
        }
        zx = wsum(zx); zy = wsum(zy);
        if (lane == 0) { s_z[parity][pair][half][0] = zx; s_z[parity][pair][half][1] = zy; }
        asm volatile("bar.sync %0, %1;" :: "r"(pair + 1), "r"(64) : "memory");
        float zi = (s_z[parity][pair][0][0] + s_z[parity][pair][1][0]) * (1.0f / D_);
        float zo = (s_z[parity][pair][0][1] + s_z[parity][pair][1][1]) * (1.0f / D_);
        float g = (b_in + a_in * __expf(-tau_in * zi)) *
                  (b_out + a_out * __expf(-tau_out * zo));
        if (half == 0 && lane == 0) g_gate[row] = g;
        const ull GA2 = pk2(g, g);
#pragma unroll
        for (int k = 0; k < 4; k++) {
            accA[k] = fma2p(Ya[k], GA2, accA[k]);
            accB[k] = fma2p(Yb[k], GA2, accB[k]);
        }

        row = rown;
        parity ^= 1;
#pragma unroll
        for (int k = 0; k < 4; k++) X[k] = NX[k];
    }

    // combine the 4 pair-accumulators (reuse s_buf; ema tables dead now)
    __syncthreads();
#pragma unroll
    for (int k = 0; k < 4; k++) {
        F4U A; A.u2.x = accA[k]; A.u2.y = accB[k];
        *(float4*)&s_buf[pair][(voff + 32 * k) * 4] = A.f4;
    }
    __syncthreads();
    {
        const int c = t * 4;
        float4 r0 = *(const float4*)&s_buf[0][c];
        float4 r1 = *(const float4*)&s_buf[1][c];
        float4 r2 = *(const float4*)&s_buf[2][c];
        float4 r3 = *(const float4*)&s_buf[3][c];
        float4 o;
        o.x = (r0.x + r1.x) + (r2.x + r3.x);
        o.y = (r0.y + r1.y) + (r2.y + r3.y);
        o.z = (r0.z + r1.z) + (r2.z + r3.z);
        o.w = (r0.w + r1.w) + (r2.w + r3.w);
        *(float4*)(g_colpart + blockIdx.x * D_ + c) = o;
    }
}

// ------ fused colreduce (128 blocks) + sims + select --------------------
__global__ void __launch_bounds__(128) k_mid(
    const float* __restrict__ buf, const float* __restrict__ facil,
    const float* __restrict__ p_lkb, const float* __restrict__ p_lkd,
    int N, float invM)
{
    const int n = blockIdx.x;
    const int t = threadIdx.x;
    const int lane = t & 31, w = t >> 5;

    if (n < 128) {
        const int col = n * 8 + (t & 7);
        const int gs = t >> 3;                 // 0..15
        float s = 0.f;
        for (int g = gs; g < GRID1; g += 16)   // ~28 slices per thread
            s += g_colpart[g * D_ + col];
        __shared__ float sm[16][8];
        sm[gs][t & 7] = s;
        __syncthreads();
        if (t < 8) {
            float tot = 0.f;
#pragma unroll
            for (int i = 0; i < 16; i++) tot += sm[i][t];
            g_mean[n * 8 + t] = tot * invM;
        }
        if (t == 0) { __threadfence(); atomicAdd(&g_ctr2, 1); }
    }
    if (t == 0) {
        while (atomicAdd(&g_ctr2, 0) < 128) { }
    }
    __syncthreads();

    const float4* bp = (const float4*)(buf + (size_t)n * D_);
    const float4* mp = (const float4*)g_mean;
    float dot = 0.f, b2 = 0.f, m2 = 0.f;
    int fin = 1;
#pragma unroll
    for (int k = 0; k < 2; k++) {
        float4 bv = bp[t + k * 128];
        float4 mv = mp[t + k * 128];
        dot = fmaf(bv.x, mv.x, fmaf(bv.y, mv.y, fmaf(bv.z, mv.z, fmaf(bv.w, mv.w, dot))));
        b2  = fmaf(bv.x, bv.x, fmaf(bv.y, bv.y, fmaf(bv.z, bv.z, fmaf(bv.w, bv.w, b2))));
        m2  = fmaf(mv.x, mv.x, fmaf(mv.y, mv.y, fmaf(mv.z, mv.z, fmaf(mv.w, mv.w, m2))));
        fin &= (fabsf(bv.x) <= 3.4028234e38f) & (fabsf(bv.y) <= 3.4028234e38f) &
               (fabsf(bv.z) <= 3.4028234e38f) & (fabsf(bv.w) <= 3.4028234e38f);
    }
    dot = wsum(dot); b2 = wsum(b2); m2 = wsum(m2);
    fin = __all_sync(0xffffffffu, fin);
    __shared__ float sd[4], sb[4], sm2[4];
    __shared__ int sf[4];
    if (lane == 0) { sd[w] = dot; sb[w] = b2; sm2[w] = m2; sf[w] = fin; }
    __syncthreads();
    if (t == 0) {
        float dt = sd[0] + sd[1] + sd[2] + sd[3];
        float bb = sb[0] + sb[1] + sb[2] + sb[3];
        float mm = sm2[0] + sm2[1] + sm2[2] + sm2[3];
        float bnorm = fmaxf(sqrtf(bb), 1e-12f);
        float mnorm = fmaxf(sqrtf(mm), 1e-12f);
        g_sims[n] = dt / (bnorm * mnorm);
        g_valid[n] = (sf[0] & sf[1] & sf[2] & sf[3]) && (sqrtf(bb) >= 1e-6f);
    }
    __shared__ int is_last;
    if (t == 0) {
        __threadfence();
        int c = atomicAdd(&g_ctr, 1);
        is_last = (c == gridDim.x - 1) ? 1 : 0;
    }
    __syncthreads();
    if (!is_last) return;

    float best = -3.0e38f; int bidx = 0x7fffffff;
    for (int i = t; i < N; i += 128) {
        float v = g_sims[i];
        if (v > best) { best = v; bidx = i; }
    }
#pragma unroll
    for (int o = 16; o > 0; o >>= 1) {
        float ov = __shfl_xor_sync(0xffffffffu, best, o);
        int   oi = __shfl_xor_sync(0xffffffffu, bidx, o);
        if (ov > best || (ov == best && oi < bidx)) { best = ov; bidx = oi; }
    }
    __shared__ float svv[4]; __shared__ int sii[4];
    if (lane == 0) { svv[w] = best; sii[w] = bidx; }
    __syncthreads();
    if (t == 0) {
        float bv = svv[0]; int bi = sii[0];
#pragma unroll
        for (int i = 1; i < 4; i++) {
            if (svv[i] > bv || (svv[i] == bv && sii[i] < bi)) { bv = svv[i]; bi = sii[i]; }
        }
        float sim_val = fminf(fmaxf(bv, 0.0f), 1.0f);
        float kb = fminf(fmaxf(expf(p_lkb[0]), 0.01f), 4.0f);
        float kd = fminf(fmaxf(expf(p_lkd[0]), 0.01f), 0.9f);
        float fl = facil[bi] * ((sim_val > 0.88f) ? 2.0f : 1.0f);
        float mod = (fl - 1.0f) * sim_val;
        float boost = 1.0f + kb * mod;
        float damp = fmaxf(0.01f, 1.0f - kd * mod);
        g_nidx = bi;
        if (g_valid[bi]) { g_damp = damp; g_qscale = (boost - damp) / damp; }
        else             { g_damp = 1.0f; g_qscale = 0.0f; }
        g_ctr = 0;
        g_ctr2 = 0;
    }
}

// ------- pass 2: warp-pair per row, register-pipelined x loads ----------
__global__ void __launch_bounds__(BLK, 4) k_pass2(
    const float* __restrict__ x, const float* __restrict__ buf,
    float* __restrict__ out, int M)
{
    __shared__ float4 s_v[D_ / 4];
    __shared__ float s_p[2][PAIRS][2];
    const int t = threadIdx.x;
    const int lane = t & 31, w = t >> 5;
    const int pair = w >> 1, half = w & 1;
    const float damp = g_damp;
    const float qscale = g_qscale;
    const int ni = g_nidx;

    {
        const float4* vp = (const float4*)(buf + (size_t)ni * D_);
        for (int i = t; i < D_ / 4; i += BLK) s_v[i] = vp[i];
    }
    __syncthreads();

    const int voff = half * 128 + lane;
    const int stride = GRID2 * PAIRS;

    int row = blockIdx.x * PAIRS + pair;
    float4 X[4];
    float ga0 = 0.f;
    if (row < M) {
        const float4* xp = (const float4*)(x + (size_t)row * D_) + voff;
#pragma unroll
        for (int k = 0; k < 4; k++) X[k] = __ldcs(xp + 32 * k);
        ga0 = g_gate[row];
    }
    int parity = 0;

    while (row < M) {
        const int rown = row + stride;
        float4 NX[4];
        float gan = 0.f;
        if (rown < M) {
            const float4* xq = (const float4*)(x + (size_t)rown * D_) + voff;
#pragma unroll
            for (int k = 0; k < 4; k++) NX[k] = __ldcs(xq + 32 * k);
            gan = g_gate[rown];
        }

        const float gad = 0.5f * damp * ga0;
        float4 Y[4];
        float proj = 0.f;
#pragma unroll
        for (int k = 0; k < 4; k++) {
            float4 Xk = X[k];
            float4 V = s_v[voff + 32 * k];
            float4 yy;
            float u0 = 0.7978845608028654f * fmaf(0.044715f * Xk.x, Xk.x * Xk.x, Xk.x);
            float u1 = 0.7978845608028654f * fmaf(0.044715f * Xk.y, Xk.y * Xk.y, Xk.y);
            float u2 = 0.7978845608028654f * fmaf(0.044715f * Xk.z, Xk.z * Xk.z, Xk.z);
            float u3 = 0.7978845608028654f * fmaf(0.044715f * Xk.w, Xk.w * Xk.w, Xk.w);
            yy.x = (Xk.x * gad) * (1.0f + tanh_ap(u0));
            yy.y = (Xk.y * gad) * (1.0f + tanh_ap(u1));
            yy.z = (Xk.z * gad) * (1.0f + tanh_ap(u2));
            yy.w = (Xk.w * gad) * (1.0f + tanh_ap(u3));
            Y[k] = yy;
            proj = fmaf(yy.x, V.x, fmaf(yy.y, V.y, fmaf(yy.z, V.z, fmaf(yy.w, V.w, proj))));
        }
        proj = wsum(proj);
        if (lane == 0) s_p[parity][pair][half] = proj;
        asm volatile("bar.sync %0, %1;" :: "r"(pair + 1), "r"(64) : "memory");
        const float q = (s_p[parity][pair][0] + s_p[parity][pair][1]) * qscale;
        float4* op = (float4*)(out + (size_t)row * D_) + voff;
#pragma unroll
        for (int k = 0; k < 4; k++) {
            float4 V = s_v[voff + 32 * k];
            float4 O;
            O.x = fmaf(q, V.x, Y[k].x);
            O.y = fmaf(q, V.y, Y[k].y);
            O.z = fmaf(q, V.z, Y[k].z);
            O.w = fmaf(q, V.w, Y[k].w);
            __stcs(op + 32 * k, O);
        }

        row = rown;
        ga0 = gan;
        parity ^= 1;
#pragma unroll
        for (int k = 0; k < 4; k++) X[k] = NX[k];
    }
}

extern "C" void kernel_launch(void* const* d_in, const int* in_sizes, int n_in,
                              void* d_out, int out_size)
{
    const float* x      = (const float*)d_in[0];
    const float* lt_in  = (const float*)d_in[1];
    const float* lt_out = (const float*)d_in[2];
    const float* la_in  = (const float*)d_in[3];
    const float* la_out = (const float*)d_in[4];
    const float* lkb    = (const float*)d_in[5];
    const float* lkd    = (const float*)d_in[6];
    const float* ema_x  = (const float*)d_in[7];
    const float* ema_x2 = (const float*)d_in[8];
    const float* ema_y  = (const float*)d_in[9];
    const float* ema_y2 = (const float*)d_in[10];
    const float* buf    = (const float*)d_in[11];
    const float* facil  = (const float*)d_in[12];

    const int M = in_sizes[0] / D_;   // 16384
    const int N = in_sizes[11] / D_;  // 512
    float* out = (float*)d_out;

    k_pass1<<<GRID1, BLK>>>(x, ema_x, ema_x2, ema_y, ema_y2,
                            lt_in, lt_out, la_in, la_out, M);
    k_mid<<<N, 128>>>(buf, facil, lkb, lkd, N, 1.0f / (float)M);
    k_pass2<<<GRID2, BLK>>>(x, buf, out, M);
}

// round 17
// speedup vs baseline: 1.0185x; 1.0185x over previous
#include <cuda_runtime.h>
#include <math.h>

#define D_     1024
#define BLK    256
#define GRID1  444        // pass1: 3 CTA/SM * 148, single wave
#define GRID2  512        // pass2: 4096 row-groups / 512 = 8 iters exact
#define PAIRS  4
#define NMAX   512
#define MMAX   16384
#define EPS_   1e-5f

typedef unsigned long long ull;
union F4U { float4 f4; ulonglong2 u2; };

// ---- scratch (static device globals; no allocation) ----
__device__ float g_colpart[GRID1 * D_];
__device__ float g_mean[D_];
__device__ float g_gate[MMAX];
__device__ float g_sims[NMAX];
__device__ int   g_valid[NMAX];
__device__ float g_damp, g_qscale;
__device__ int   g_nidx;
__device__ int   g_ctr = 0;
__device__ int   g_ctr2 = 0;

// ---- packed f32x2 helpers ----
__device__ __forceinline__ ull pk2(float lo, float hi) {
    ull r; asm("mov.b64 %0, {%1, %2};" : "=l"(r) : "f"(lo), "f"(hi)); return r;
}
__device__ __forceinline__ float2 upk2(ull v) {
    float2 f; asm("mov.b64 {%0, %1}, %2;" : "=f"(f.x), "=f"(f.y) : "l"(v)); return f;
}
__device__ __forceinline__ ull fma2p(ull a, ull b, ull c) {
    ull r; asm("fma.rn.f32x2 %0, %1, %2, %3;" : "=l"(r) : "l"(a), "l"(b), "l"(c)); return r;
}
__device__ __forceinline__ ull mul2p(ull a, ull b) {
    ull r; asm("mul.rn.f32x2 %0, %1, %2;" : "=l"(r) : "l"(a), "l"(b)); return r;
}
__device__ __forceinline__ float wsum(float v) {
    v += __shfl_xor_sync(0xffffffffu, v, 16);
    v += __shfl_xor_sync(0xffffffffu, v, 8);
    v += __shfl_xor_sync(0xffffffffu, v, 4);
    v += __shfl_xor_sync(0xffffffffu, v, 2);
    v += __shfl_xor_sync(0xffffffffu, v, 1);
    return v;
}
__device__ __forceinline__ float tanh_ap(float u) {
    float r; asm("tanh.approx.f32 %0, %1;" : "=f"(r) : "f"(u)); return r;
}
__device__ __forceinline__ ull gelu2p(ull x2) {
    const ull A2   = pk2(0.044715f, 0.044715f);
    const ull ONE2 = pk2(1.0f, 1.0f);
    const ull C2   = pk2(0.7978845608028654f, 0.7978845608028654f);
    const ull H2   = pk2(0.5f, 0.5f);
    ull t2 = mul2p(x2, x2);
    ull p2 = fma2p(t2, A2, ONE2);
    ull u2 = mul2p(mul2p(x2, C2), p2);
    float2 u = upk2(u2);
    ull T2 = pk2(tanh_ap(u.x), tanh_ap(u.y));
    ull hx2 = mul2p(x2, H2);
    return fma2p(T2, hx2, hx2);
}

// ------ pass 1: warp-pair per row, no block barrier in mainloop ---------
__global__ void __launch_bounds__(BLK, 3) k_pass1(
    const float* __restrict__ x,
    const float* __restrict__ ema_x, const float* __restrict__ ema_x2,
    const float* __restrict__ ema_y, const float* __restrict__ ema_y2,
    const float* __restrict__ p_lt_in, const float* __restrict__ p_lt_out,
    const float* __restrict__ p_la_in, const float* __restrict__ p_la_out,
    int M)
{
    __shared__ float s_buf[4][D_];          // isx / nx / isy / ny, later acc staging
    __shared__ float s_z[2][PAIRS][2][2];   // [parity][pair][half][zx,zy]
    const int t = threadIdx.x;
    const int lane = t & 31, w = t >> 5;
    const int pair = w >> 1, half = w & 1;

    // build ema stat tables in shared (thread t owns cols 4t..4t+3)
    {
        const int c = t * 4;
        float4 ex = *(const float4*)(ema_x + c);
        float4 e2 = *(const float4*)(ema_x2 + c);
        float4 ey = *(const float4*)(ema_y + c);
        float4 f2 = *(const float4*)(ema_y2 + c);
        float4 is, nx, isy, ny;
        is.x = 1.0f / (sqrtf(fmaxf(e2.x - ex.x * ex.x, 0.0f)) + EPS_);
        is.y = 1.0f / (sqrtf(fmaxf(e2.y - ex.y * ex.y, 0.0f)) + EPS_);
        is.z = 1.0f / (sqrtf(fmaxf(e2.z - ex.z * ex.z, 0.0f)) + EPS_);
        is.w = 1.0f / (sqrtf(fmaxf(e2.w - ex.w * ex.w, 0.0f)) + EPS_);
        isy.x = 1.0f / (sqrtf(fmaxf(f2.x - ey.x * ey.x, 0.0f)) + EPS_);
        isy.y = 1.0f / (sqrtf(fmaxf(f2.y - ey.y * ey.y, 0.0f)) + EPS_);
        isy.z = 1.0f / (sqrtf(fmaxf(f2.z - ey.z * ey.z, 0.0f)) + EPS_);
        isy.w = 1.0f / (sqrtf(fmaxf(f2.w - ey.w * ey.w, 0.0f)) + EPS_);
        nx.x = -ex.x * is.x; nx.y = -ex.y * is.y; nx.z = -ex.z * is.z; nx.w = -ex.w * is.w;
        ny.x = -ey.x * isy.x; ny.y = -ey.y * isy.y; ny.z = -ey.z * isy.z; ny.w = -ey.w * isy.w;
        *(float4*)&s_buf[0][c] = is;
        *(float4*)&s_buf[1][c] = nx;
        *(float4*)&s_buf[2][c] = isy;
        *(float4*)&s_buf[3][c] = ny;
    }
    const float tau_in  = expf(p_lt_in[0]);
    const float tau_out = expf(p_lt_out[0]);
    const float a_in    = 1.0f / (1.0f + expf(-p_la_in[0]));
    const float a_out   = 1.0f / (1.0f + expf(-p_la_out[0]));
    const float b_in = 1.0f - a_in, b_out = 1.0f - a_out;
    __syncthreads();

    const int voff = half * 128 + lane;      // float4 index within row
    const int stride = GRID1 * PAIRS;

    ull accA[4], accB[4];
#pragma unroll
    for (int k = 0; k < 4; k++) { accA[k] = 0ull; accB[k] = 0ull; }

    int row = blockIdx.x * PAIRS + pair;
    float4 X[4];
    if (row < M) {
        const float4* xp = (const float4*)(x + (size_t)row * D_) + voff;
#pragma unroll
        for (int k = 0; k < 4; k++) X[k] = xp[32 * k];
    }
    int parity = 0;

    while (row < M) {
        const int rown = row + stride;
        float4 NX[4];
        if (rown < M) {
            const float4* xq = (const float4*)(x + (size_t)rown * D_) + voff;
#pragma unroll
            for (int k = 0; k < 4; k++) NX[k] = xq[32 * k];
        }

        ull Ya[4], Yb[4];
        float zx = 0.f, zy = 0.f;
#pragma unroll
        for (int k = 0; k < 4; k++) {
            F4U Xu; Xu.f4 = X[k];
            ull y0 = gelu2p(Xu.u2.x);
            ull y1 = gelu2p(Xu.u2.y);
            Ya[k] = y0; Yb[k] = y1;
            F4U IS;  IS.f4  = *(const float4*)&s_buf[0][(voff + 32 * k) * 4];
            F4U NXc; NXc.f4 = *(const float4*)&s_buf[1][(voff + 32 * k) * 4];
            F4U ISY; ISY.f4 = *(const float4*)&s_buf[2][(voff + 32 * k) * 4];
            F4U NYc; NYc.f4 = *(const float4*)&s_buf[3][(voff + 32 * k) * 4];
            ull da = fma2p(Xu.u2.x, IS.u2.x, NXc.u2.x);
            ull db = fma2p(Xu.u2.y, IS.u2.y, NXc.u2.y);
            ull sx = fma2p(db, db, mul2p(da, da));
            float2 fx = upk2(sx); zx += fx.x + fx.y;
            ull ga_ = fma2p(y0, ISY.u2.x, NYc.u2.x);
            ull gb_ = fma2p(y1, ISY.u2.y, NYc.u2.y);
            ull sy = fma2p(gb_, gb_, mul2p(ga_, ga_));
            float2 fy = upk2(sy); zy += fy.x + fy.y;
        }
        zx = wsum(zx); zy = wsum(zy);
        if (lane == 0) { s_z[parity][pair][half][0] = zx; s_z[parity][pair][half][1] = zy; }
        asm volatile("bar.sync %0, %1;" :: "r"(pair + 1), "r"(64) : "memory");
        float zi = (s_z[parity][pair][0][0] + s_z[parity][pair][1][0]) * (1.0f / D_);
        float zo = (s_z[parity][pair][0][1] + s_z[parity][pair][1][1]) * (1.0f / D_);
        float g = (b_in + a_in * __expf(-tau_in * zi)) *
                  (b_out + a_out * __expf(-tau_out * zo));
        if (half == 0 && lane == 0) g_gate[row] = g;
        const ull GA2 = pk2(g, g);
#pragma unroll
        for (int k = 0; k < 4; k++) {
            accA[k] = fma2p(Ya[k], GA2, accA[k]);
            accB[k] = fma2p(Yb[k], GA2, accB[k]);
        }

        row = rown;
        parity ^= 1;
#pragma unroll
        for (int k = 0; k < 4; k++) X[k] = NX[k];
    }

    // combine the 4 pair-accumulators (reuse s_buf; ema tables dead now)
    __syncthreads();
#pragma unroll
    for (int k = 0; k < 4; k++) {
        F4U A; A.u2.x = accA[k]; A.u2.y = accB[k];
        *(float4*)&s_buf[pair][(voff + 32 * k) * 4] = A.f4;
    }
    __syncthreads();
    {
        const int c = t * 4;
        float4 r0 = *(const float4*)&s_buf[0][c];
        float4 r1 = *(const float4*)&s_buf[1][c];
        float4 r2 = *(const float4*)&s_buf[2][c];
        float4 r3 = *(const float4*)&s_buf[3][c];
        float4 o;
        o.x = (r0.x + r1.x) + (r2.x + r3.x);
        o.y = (r0.y + r1.y) + (r2.y + r3.y);
        o.z = (r0.z + r1.z) + (r2.z + r3.z);
        o.w = (r0.w + r1.w) + (r2.w + r3.w);
        *(float4*)(g_colpart + blockIdx.x * D_ + c) = o;
    }
}

// ------ fused colreduce (128 blocks, unrolled predicated) + sims --------
__global__ void __launch_bounds__(128) k_mid(
    const float* __restrict__ buf, const float* __restrict__ facil,
    const float* __restrict__ p_lkb, const float* __restrict__ p_lkd,
    int N, float invM)
{
    const int n = blockIdx.x;
    const int t = threadIdx.x;
    const int lane = t & 31, w = t >> 5;

    if (n < 128) {
        const int col = n * 8 + (t & 7);
        const int gs = t >> 3;                 // 0..15
        float s = 0.f;
#pragma unroll
        for (int k = 0; k < 28; k++) {         // ceil(444/16)=28, predicated
            int g = gs + k * 16;
            float v = (g < GRID1) ? g_colpart[g * D_ + col] : 0.0f;
            s += v;
        }
        __shared__ float sm[16][8];
        sm[gs][t & 7] = s;
        __syncthreads();
        if (t < 8) {
            float tot = 0.f;
#pragma unroll
            for (int i = 0; i < 16; i++) tot += sm[i][t];
            g_mean[n * 8 + t] = tot * invM;
        }
        if (t == 0) { __threadfence(); atomicAdd(&g_ctr2, 1); }
    }
    if (t == 0) {
        while (atomicAdd(&g_ctr2, 0) < 128) { }
    }
    __syncthreads();

    const float4* bp = (const float4*)(buf + (size_t)n * D_);
    const float4* mp = (const float4*)g_mean;
    float dot = 0.f, b2 = 0.f, m2 = 0.f;
    int fin = 1;
#pragma unroll
    for (int k = 0; k < 2; k++) {
        float4 bv = bp[t + k * 128];
        float4 mv = mp[t + k * 128];
        dot = fmaf(bv.x, mv.x, fmaf(bv.y, mv.y, fmaf(bv.z, mv.z, fmaf(bv.w, mv.w, dot))));
        b2  = fmaf(bv.x, bv.x, fmaf(bv.y, bv.y, fmaf(bv.z, bv.z, fmaf(bv.w, bv.w, b2))));
        m2  = fmaf(mv.x, mv.x, fmaf(mv.y, mv.y, fmaf(mv.z, mv.z, fmaf(mv.w, mv.w, m2))));
        fin &= (fabsf(bv.x) <= 3.4028234e38f) & (fabsf(bv.y) <= 3.4028234e38f) &
               (fabsf(bv.z) <= 3.4028234e38f) & (fabsf(bv.w) <= 3.4028234e38f);
    }
    dot = wsum(dot); b2 = wsum(b2); m2 = wsum(m2);
    fin = __all_sync(0xffffffffu, fin);
    __shared__ float sd[4], sb[4], sm2[4];
    __shared__ int sf[4];
    if (lane == 0) { sd[w] = dot; sb[w] = b2; sm2[w] = m2; sf[w] = fin; }
    __syncthreads();
    if (t == 0) {
        float dt = sd[0] + sd[1] + sd[2] + sd[3];
        float bb = sb[0] + sb[1] + sb[2] + sb[3];
        float mm = sm2[0] + sm2[1] + sm2[2] + sm2[3];
        float bnorm = fmaxf(sqrtf(bb), 1e-12f);
        float mnorm = fmaxf(sqrtf(mm), 1e-12f);
        g_sims[n] = dt / (bnorm * mnorm);
        g_valid[n] = (sf[0] & sf[1] & sf[2] & sf[3]) && (sqrtf(bb) >= 1e-6f);
    }
    __shared__ int is_last;
    if (t == 0) {
        __threadfence();
        int c = atomicAdd(&g_ctr, 1);
        is_last = (c == gridDim.x - 1) ? 1 : 0;
    }
    __syncthreads();
    if (!is_last) return;

    float best = -3.0e38f; int bidx = 0x7fffffff;
    for (int i = t; i < N; i += 128) {
        float v = g_sims[i];
        if (v > best) { best = v; bidx = i; }
    }
#pragma unroll
    for (int o = 16; o > 0; o >>= 1) {
        float ov = __shfl_xor_sync(0xffffffffu, best, o);
        int   oi = __shfl_xor_sync(0xffffffffu, bidx, o);
        if (ov > best || (ov == best && oi < bidx)) { best = ov; bidx = oi; }
    }
    __shared__ float svv[4]; __shared__ int sii[4];
    if (lane == 0) { svv[w] = best; sii[w] = bidx; }
    __syncthreads();
    if (t == 0) {
        float bv = svv[0]; int bi = sii[0];
#pragma unroll
        for (int i = 1; i < 4; i++) {
            if (svv[i] > bv || (svv[i] == bv && sii[i] < bi)) { bv = svv[i]; bi = sii[i]; }
        }
        float sim_val = fminf(fmaxf(bv, 0.0f), 1.0f);
        float kb = fminf(fmaxf(expf(p_lkb[0]), 0.01f), 4.0f);
        float kd = fminf(fmaxf(expf(p_lkd[0]), 0.01f), 0.9f);
        float fl = facil[bi] * ((sim_val > 0.88f) ? 2.0f : 1.0f);
        float mod = (fl - 1.0f) * sim_val;
        float boost = 1.0f + kb * mod;
        float damp = fmaxf(0.01f, 1.0f - kd * mod);
        g_nidx = bi;
        if (g_valid[bi]) { g_damp = damp; g_qscale = (boost - damp) / damp; }
        else             { g_damp = 1.0f; g_qscale = 0.0f; }
        g_ctr = 0;
        g_ctr2 = 0;
    }
}

// ------- pass 2: warp-pair per row, register-pipelined x loads ----------
__global__ void __launch_bounds__(BLK, 4) k_pass2(
    const float* __restrict__ x, const float* __restrict__ buf,
    float* __restrict__ out, int M)
{
    __shared__ float4 s_v[D_ / 4];
    __shared__ float s_p[2][PAIRS][2];
    const int t = threadIdx.x;
    const int lane = t & 31, w = t >> 5;
    const int pair = w >> 1, half = w & 1;
    const float damp = g_damp;
    const float qscale = g_qscale;
    const int ni = g_nidx;

    {
        const float4* vp = (const float4*)(buf + (size_t)ni * D_);
        for (int i = t; i < D_ / 4; i += BLK) s_v[i] = vp[i];
    }
    __syncthreads();

    const int voff = half * 128 + lane;
    const int stride = GRID2 * PAIRS;

    int row = blockIdx.x * PAIRS + pair;
    float4 X[4];
    float ga0 = 0.f;
    if (row < M) {
        const float4* xp = (const float4*)(x + (size_t)row * D_) + voff;
#pragma unroll
        for (int k = 0; k < 4; k++) X[k] = __ldcs(xp + 32 * k);
        ga0 = g_gate[row];
    }
    int parity = 0;

    while (row < M) {
        const int rown = row + stride;
        float4 NX[4];
        float gan = 0.f;
        if (rown < M) {
            const float4* xq = (const float4*)(x + (size_t)rown * D_) + voff;
#pragma unroll
            for (int k = 0; k < 4; k++) NX[k] = __ldcs(xq + 32 * k);
            gan = g_gate[rown];
        }

        const float gad = 0.5f * damp * ga0;
        float4 Y[4];
        float proj = 0.f;
#pragma unroll
        for (int k = 0; k < 4; k++) {
            float4 Xk = X[k];
            float4 V = s_v[voff + 32 * k];
            float4 yy;
            float u0 = 0.7978845608028654f * fmaf(0.044715f * Xk.x, Xk.x * Xk.x, Xk.x);
            float u1 = 0.7978845608028654f * fmaf(0.044715f * Xk.y, Xk.y * Xk.y, Xk.y);
            float u2 = 0.7978845608028654f * fmaf(0.044715f * Xk.z, Xk.z * Xk.z, Xk.z);
            float u3 = 0.7978845608028654f * fmaf(0.044715f * Xk.w, Xk.w * Xk.w, Xk.w);
            yy.x = (Xk.x * gad) * (1.0f + tanh_ap(u0));
            yy.y = (Xk.y * gad) * (1.0f + tanh_ap(u1));
            yy.z = (Xk.z * gad) * (1.0f + tanh_ap(u2));
            yy.w = (Xk.w * gad) * (1.0f + tanh_ap(u3));
            Y[k] = yy;
            proj = fmaf(yy.x, V.x, fmaf(yy.y, V.y, fmaf(yy.z, V.z, fmaf(yy.w, V.w, proj))));
        }
        proj = wsum(proj);
        if (lane == 0) s_p[parity][pair][half] = proj;
        asm volatile("bar.sync %0, %1;" :: "r"(pair + 1), "r"(64) : "memory");
        const float q = (s_p[parity][pair][0] + s_p[parity][pair][1]) * qscale;
        float4* op = (float4*)(out + (size_t)row * D_) + voff;
#pragma unroll
        for (int k = 0; k < 4; k++) {
            float4 V = s_v[voff + 32 * k];
            float4 O;
            O.x = fmaf(q, V.x, Y[k].x);
            O.y = fmaf(q, V.y, Y[k].y);
            O.z = fmaf(q, V.z, Y[k].z);
            O.w = fmaf(q, V.w, Y[k].w);
            __stcs(op + 32 * k, O);
        }

        row = rown;
        ga0 = gan;
        parity ^= 1;
#pragma unroll
        for (int k = 0; k < 4; k++) X[k] = NX[k];
    }
}

extern "C" void kernel_launch(void* const* d_in, const int* in_sizes, int n_in,
                              void* d_out, int out_size)
{
    const float* x      = (const float*)d_in[0];
    const float* lt_in  = (const float*)d_in[1];
    const float* lt_out = (const float*)d_in[2];
    const float* la_in  = (const float*)d_in[3];
    const float* la_out = (const float*)d_in[4];
    const float* lkb    = (const float*)d_in[5];
    const float* lkd    = (const float*)d_in[6];
    const float* ema_x  = (const float*)d_in[7];
    const float* ema_x2 = (const float*)d_in[8];
    const float* ema_y  = (const float*)d_in[9];
    const float* ema_y2 = (const float*)d_in[10];
    const float* buf    = (const float*)d_in[11];
    const float* facil  = (const float*)d_in[12];

    const int M = in_sizes[0] / D_;   // 16384
    const int N = in_sizes[11] / D_;  // 512
    float* out = (float*)d_out;

    k_pass1<<<GRID1, BLK>>>(x, ema_x, ema_x2, ema_y, ema_y2,
                            lt_in, lt_out, la_in, la_out, M);
    k_mid<<<N, 128>>>(buf, facil, lkb, lkd, N, 1.0f / (float)M);
    k_pass2<<<GRID2, BLK>>>(x, buf, out, M);
}